// round 3
// baseline (speedup 1.0000x reference)
#include <cuda_runtime.h>
#include <cstdint>

#define N_STFT   1025
#define N_MELS   128
#define BATCH    4
#define TIME     1024
#define ROWS     (BATCH*TIME)
#define MAX_ITER 20
#define LR       0.3f
#define MOM      0.9f
#define INV      (2.0f/4096.0f)
#define CH       33          // frequencies per lane (32*33 >= 1025)
#define WPB      8           // warps (rows) per block

// ---------------- device globals (no allocation allowed) ----------------
__device__ float         g_w0t[N_STFT];
__device__ float         g_w1t[N_STFT];
__device__ unsigned char g_mbt[N_STFT];
__device__ float         g_spec[ROWS * N_STFT];   // (B,T,F) scratch, ~16.8 MB

// ---------------- table build: per-frequency sparse rep of fb ----------------
// fb row f has <=2 nonzeros at adjacent mels (triangular filterbank).
__global__ void build_tables_k(const float* __restrict__ fb) {
    int f = blockIdx.x * blockDim.x + threadIdx.x;
    if (f >= N_STFT) return;
    const float* r = fb + (size_t)f * N_MELS;
    int m0 = -1;
    for (int m = 0; m < N_MELS; m++) {
        if (r[m] != 0.0f) { m0 = m; break; }
    }
    float w0 = 0.f, w1 = 0.f; int mm = 0;
    if (m0 >= 0) {
        mm = m0;
        w0 = r[m0];
        w1 = (m0 < N_MELS - 1) ? r[m0 + 1] : 0.f;
    }
    g_w0t[f] = w0; g_w1t[f] = w1; g_mbt[f] = (unsigned char)mm;
}

// ---------------- helpers ----------------
__device__ __forceinline__ unsigned smem_u32(const void* p) {
    return (unsigned)__cvta_generic_to_shared(p);
}
// predicated shared-memory reduction add (single instruction, no BSSY/BSYNC)
__device__ __forceinline__ void pred_red(unsigned addr, float v, int pred) {
    asm volatile("{\n\t.reg .pred p;\n\tsetp.ne.s32 p, %2, 0;\n\t"
                 "@p red.shared.add.f32 [%0], %1;\n\t}"
                 :: "r"(addr), "f"(v), "r"(pred) : "memory");
}
__device__ __forceinline__ void red_add(unsigned addr, float v) {
    asm volatile("red.shared.add.f32 [%0], %1;" :: "r"(addr), "f"(v) : "memory");
}
// predicated pair load from shared; keeps old values when pred==0
__device__ __forceinline__ void pred_ld2(unsigned addr, int pred, float& d0, float& d1) {
    asm volatile("{\n\t.reg .pred p;\n\tsetp.ne.s32 p, %3, 0;\n\t"
                 "@p ld.shared.f32 %0, [%2];\n\t"
                 "@p ld.shared.f32 %1, [%2+4];\n\t}"
                 : "+f"(d0), "+f"(d1) : "r"(addr), "r"(pred) : "memory");
}

// extract mel index i (compile-time i after unroll) from byte-packed regs
#define EXT(i) ((int)((mpk[(i) >> 2] >> (((i) & 3) * 8)) & 0xFFu))

// forward step: run-length accumulate into (a0 -> mc, a1 -> mc+1), flush on mel change
#define FWD_STEP(i, mc, a0, a1) do {                                        \
    int mi_ = EXT(i);                                                       \
    int ch_ = (mi_ != (mc));                                                \
    pred_red(pa + (unsigned)(mc) * 4u, (a0), ch_);                          \
    pred_red(pa + (unsigned)((mc) + 1) * 4u, (a1), ch_ & (int)(mi_ != (mc) + 1)); \
    float n0_ = (mi_ == (mc) + 1) ? (a1) : 0.f;                             \
    (a0) = ch_ ? n0_ : (a0);                                                \
    (a1) = ch_ ? 0.f : (a1);                                                \
    (mc) = mi_;                                                             \
    (a0) = fmaf(sp[(i)], w0[(i)], (a0));                                    \
    (a1) = fmaf(sp[(i)], w1[(i)], (a1));                                    \
} while (0)

// backward step: reload diff pair only when mel changes, then momentum update + clamp
#define BWD_STEP(i, mb, d0, d1) do {                                        \
    int mi_ = EXT(i);                                                       \
    int ch_ = (mi_ != (mb));                                                \
    pred_ld2(pa + (unsigned)mi_ * 4u, ch_, (d0), (d1));                     \
    (mb) = mi_;                                                             \
    float g_ = fmaf((d1), w1[(i)], (d0) * w0[(i)]);                         \
    bu[(i)] = fmaf(MOM, bu[(i)], -INV * g_);                                \
    sp[(i)] = fmaxf(fmaf(-LR, bu[(i)], sp[(i)]), 0.f);                      \
} while (0)

// ---------------- main: one warp per (b,t) row, 20 iterations in-register ----------------
__global__ void __launch_bounds__(32 * WPB, 1)
imel_main_k(const float* __restrict__ mel, const float* __restrict__ spec_init) {
    __shared__ float s_proj[WPB][136];   // per-warp proj/diff (128) + pads

    const int wid  = threadIdx.x >> 5;
    const int lane = threadIdx.x & 31;
    const int row  = blockIdx.x * WPB + wid;          // 0..4095
    const int b    = row >> 10;
    const int t    = row & (TIME - 1);

    float* proj = s_proj[wid];
    const unsigned pa = smem_u32(proj);

    const int f_lo = lane * CH;

    // register-resident state
    float w0[CH], w1[CH], sp[CH], bu[CH];
    unsigned mpk[9];

    #pragma unroll
    for (int i = 0; i < CH; i++) {
        int f  = f_lo + i;
        int fc = (f > N_STFT - 1) ? (N_STFT - 1) : f;
        bool v = (f <= N_STFT - 1);
        w0[i] = v ? g_w0t[fc] : 0.f;
        w1[i] = v ? g_w1t[fc] : 0.f;
        sp[i] = spec_init[row * N_STFT + fc];   // duplicate at clamp is never stored
        bu[i] = 0.f;
    }
    #pragma unroll
    for (int j = 0; j < 9; j++) {
        unsigned v = 0;
        #pragma unroll
        for (int k = 0; k < 4; k++) {
            int i = 4 * j + k; if (i > CH - 1) i = CH - 1;
            int f = f_lo + i;  if (f > N_STFT - 1) f = N_STFT - 1;
            v |= (unsigned)g_mbt[f] << (8 * k);
        }
        mpk[j] = v;
    }
    // this lane owns mels m = lane + 32*j (stride-1 across lanes -> conflict-free)
    float melr[4];
    #pragma unroll
    for (int j = 0; j < 4; j++)
        melr[j] = mel[b * (N_MELS * TIME) + (lane + 32 * j) * TIME + t];

    #pragma unroll 1
    for (int it = 0; it < MAX_ITER; it++) {
        // ---- zero proj (incl. pads) ----
        #pragma unroll
        for (int j = 0; j < 4; j++) proj[lane + 32 * j] = 0.f;
        if (lane < 8) proj[128 + lane] = 0.f;
        __syncwarp();

        // ---- forward: proj[m] += sum_f spec_f * fb[f,m]; 2 independent chains ----
        int   mcA = EXT(0), mcB = EXT(17);
        float a0A = 0.f, a1A = 0.f, a0B = 0.f, a1B = 0.f;
        #pragma unroll
        for (int k = 0; k < 17; k++) {
            FWD_STEP(k, mcA, a0A, a1A);
            if (k < 16) FWD_STEP(k + 17, mcB, a0B, a1B);
        }
        red_add(pa + (unsigned)mcA * 4u, a0A);
        red_add(pa + (unsigned)(mcA + 1) * 4u, a1A);
        red_add(pa + (unsigned)mcB * 4u, a0B);
        red_add(pa + (unsigned)(mcB + 1) * 4u, a1B);
        __syncwarp();

        // ---- diff in place: diff[m] = mel[m] - proj[m] (lane-exclusive slots) ----
        #pragma unroll
        for (int j = 0; j < 4; j++) {
            int m = lane + 32 * j;
            proj[m] = melr[j] - proj[m];
        }
        __syncwarp();

        // ---- backward + momentum + clamp; 2 independent chains ----
        int   mbA = -1, mbB = -1;
        float d0A = 0.f, d1A = 0.f, d0B = 0.f, d1B = 0.f;
        #pragma unroll
        for (int k = 0; k < 17; k++) {
            BWD_STEP(k, mbA, d0A, d1A);
            if (k < 16) BWD_STEP(k + 17, mbB, d0B, d1B);
        }
        __syncwarp();
    }

    // ---- write converged spec row to (B,T,F) scratch ----
    #pragma unroll
    for (int i = 0; i < CH; i++) {
        int f = f_lo + i;
        if (f < N_STFT) g_spec[row * N_STFT + f] = sp[i];
    }
}

// ---------------- transpose (B,T,F) -> (B,F,T) into d_out ----------------
__global__ void transpose_k(float* __restrict__ out) {
    __shared__ float tile[32][33];
    const int b  = blockIdx.z;
    const int t0 = blockIdx.x * 32;
    const int f0 = blockIdx.y * 32;
    const int tx = threadIdx.x, ty = threadIdx.y;

    const float* in = g_spec + (size_t)b * TIME * N_STFT;
    float*       o  = out    + (size_t)b * N_STFT * TIME;

    #pragma unroll
    for (int j = 0; j < 32; j += 8) {
        int f = f0 + tx, t = t0 + ty + j;
        if (f < N_STFT) tile[ty + j][tx] = in[t * N_STFT + f];
    }
    __syncthreads();
    #pragma unroll
    for (int j = 0; j < 32; j += 8) {
        int f = f0 + ty + j, t = t0 + tx;
        if (f < N_STFT) o[f * TIME + t] = tile[tx][ty + j];
    }
}

// ---------------- launch ----------------
extern "C" void kernel_launch(void* const* d_in, const int* in_sizes, int n_in,
                              void* d_out, int out_size) {
    // identify inputs robustly by element count
    const float* mel = nullptr;   // 4*128*1024   = 524288
    const float* spi = nullptr;   // 4*1024*1025  = 4198400
    const float* fb  = nullptr;   // 1025*128     = 131200
    for (int i = 0; i < n_in; i++) {
        if      (in_sizes[i] == BATCH * N_MELS * TIME) mel = (const float*)d_in[i];
        else if (in_sizes[i] == ROWS * N_STFT)         spi = (const float*)d_in[i];
        else if (in_sizes[i] == N_STFT * N_MELS)       fb  = (const float*)d_in[i];
    }
    float* out = (float*)d_out;

    build_tables_k<<<(N_STFT + 127) / 128, 128>>>(fb);
    imel_main_k<<<ROWS / WPB, 32 * WPB>>>(mel, spi);
    dim3 tg(TIME / 32, (N_STFT + 31) / 32, BATCH), tb(32, 8);
    transpose_k<<<tg, tb>>>(out);
}

// round 4
// speedup vs baseline: 4.1467x; 4.1467x over previous
#include <cuda_runtime.h>
#include <cstdint>

#define N_STFT   1025
#define N_MELS   128
#define BATCH    4
#define TIME     1024
#define ROWS     (BATCH*TIME)
#define MAX_ITER 20
#define LR       0.3f
#define MOM      0.9f
#define INVC     (2.0f/4096.0f)
#define CH       33            // frequency bins per lane (32*33 = 1056 >= 1025)
#define WPB      4             // warps (rows) per CTA
#define FPAD     (32*CH)       // 1056

// ---------------- device globals ----------------
__device__ float2        g_w01[FPAD];     // (w0,w1) per frequency, zero tail
__device__ unsigned char g_mbt[N_STFT];   // first-nonzero mel per frequency

// ---------------- table build: one warp per frequency ----------------
__global__ void build_tables_k(const float* __restrict__ fb) {
    int gw   = (blockIdx.x * blockDim.x + threadIdx.x) >> 5;
    int lane = threadIdx.x & 31;
    if (gw >= FPAD) return;
    if (gw >= N_STFT) { if (!lane) g_w01[gw] = make_float2(0.f, 0.f); return; }
    const float* r = fb + (size_t)gw * N_MELS;
    int m4 = lane * 4;
    unsigned loc = 128u;
    #pragma unroll
    for (int k = 3; k >= 0; k--) if (r[m4 + k] != 0.f) loc = (unsigned)(m4 + k);
    #pragma unroll
    for (int o = 16; o; o >>= 1) {
        unsigned v = __shfl_xor_sync(0xffffffffu, loc, o);
        loc = v < loc ? v : loc;
    }
    if (!lane) {
        float w0 = 0.f, w1 = 0.f; int mm = 0;
        if (loc < 128u) {
            mm = (int)loc;
            w0 = r[loc];
            w1 = (loc < 127u) ? r[loc + 1] : 0.f;
        }
        g_w01[gw] = make_float2(w0, w1);
        g_mbt[gw] = (unsigned char)mm;
    }
}

// ---------------- asm helpers (predicated, branch-free) ----------------
__device__ __forceinline__ unsigned smaddr(const void* p) {
    return (unsigned)__cvta_generic_to_shared(p);
}
__device__ __forceinline__ void sts_f32(unsigned a, float v) {
    asm volatile("st.shared.f32 [%0], %1;" :: "r"(a), "f"(v) : "memory");
}
__device__ __forceinline__ float lds_f32(unsigned a) {
    float v; asm volatile("ld.shared.f32 %0, [%1];" : "=f"(v) : "r"(a)); return v;
}
__device__ __forceinline__ void pred_sts(unsigned a, float v, int p) {
    asm volatile("{\n\t.reg .pred q;\n\tsetp.ne.s32 q, %2, 0;\n\t"
                 "@q st.shared.f32 [%0], %1;\n\t}"
                 :: "r"(a), "f"(v), "r"(p) : "memory");
}
__device__ __forceinline__ void pred_lds(float& d, unsigned a, int p) {
    asm volatile("{\n\t.reg .pred q;\n\tsetp.ne.s32 q, %2, 0;\n\t"
                 "@q ld.shared.f32 %0, [%1];\n\t}"
                 : "+f"(d) : "r"(a), "r"(p) : "memory");
}

// ---------------- shared layout: iteration phase / epilogue stage union ----------------
struct __align__(16) SmemIter {
    float  acc[WPB][132][4];   // 4 write-slots per mel, statically collision-free
    float  diff[WPB][132];
    float2 w01[FPAD];
};
union __align__(16) SmemU {
    SmemIter it;
    float    stage[WPB][FPAD];
};

// ---------------- main: warp = one (b,t) row; 20 fused iterations ----------------
__global__ void __launch_bounds__(WPB*32, 4)
imel_k(const float* __restrict__ mel, const float* __restrict__ spi,
       float* __restrict__ out)
{
    __shared__ SmemU S;
    const int tid  = threadIdx.x;
    const int wid  = tid >> 5;
    const int lane = tid & 31;
    const int row  = blockIdx.x * WPB + wid;
    const int b    = row >> 10;
    const int t    = row & (TIME - 1);

    // cooperative load of (w0,w1) table (row-invariant)
    for (int k = tid; k < FPAD; k += WPB*32) S.it.w01[k] = g_w01[k];

    // one-time zero of acc slots (static write pattern -> never re-zeroed) + diff pads
    {
        float4 z = make_float4(0.f, 0.f, 0.f, 0.f);
        for (int k = lane; k < 132; k += 32)
            *reinterpret_cast<float4*>(&S.it.acc[wid][k][0]) = z;
        if (lane < 4) S.it.diff[wid][128 + lane] = 0.f;
    }

    const int f_lo = lane * CH;
    float sp[CH], bu[CH];
    unsigned mask = 0;     // bit (i-1): mel changes between bin i-1 and i (monotone +1)
    int mfirst = 0;
    {
        int pm = 0;
        #pragma unroll
        for (int i = 0; i < CH; i++) {
            int f  = f_lo + i;
            int fc = f > N_STFT-1 ? N_STFT-1 : f;
            sp[i] = spi[(size_t)row * N_STFT + fc];
            bu[i] = 0.f;
            int m = (int)g_mbt[fc];
            if (i == 0) { mfirst = m; pm = m; }
            else {
                if (m < pm) m = pm;              // clamp zero-weight tail rows monotone
                if (m != pm) mask |= (1u << (i-1));
                pm = m;
            }
        }
    }
    float melI[4];
    #pragma unroll
    for (int j = 0; j < 4; j++)
        melI[j] = mel[(size_t)b*(N_MELS*TIME) + (size_t)(lane + 32*j)*TIME + t] * INVC;

    __syncthreads();

    const unsigned accb  = smaddr(&S.it.acc[wid][0][0]);
    const unsigned diffb = smaddr(&S.it.diff[wid][0]);
    const float2*  w01   = S.it.w01;
    // end-flush slot offsets: lanes 0..30 -> slot1 (mlast) & slot2 (mlast+1); lane31 -> slot3
    const unsigned eo0 = (lane == 31) ? 12u : 4u;
    const unsigned eo1 = (lane == 31) ? 28u : 24u;

    // ---- prologue forward: scatter proj of iteration 0 ----
    {
        unsigned aaddr = accb + (unsigned)mfirst * 16u;
        float a0 = 0.f, a1 = 0.f;
        #pragma unroll
        for (int i = 0; i < CH; i++) {
            if (i > 0) {
                int ch = (int)((mask >> (i-1)) & 1u);
                pred_sts(aaddr, a0, ch);          // flush completed mel -> slot0
                a0 = ch ? a1 : a0;                // merge: a1 becomes new a0 (dmel==1)
                a1 = ch ? 0.f : a1;
                aaddr += (unsigned)ch << 4;
            }
            float2 w = w01[f_lo + i];
            a0 = fmaf(sp[i], w.x, a0);
            a1 = fmaf(sp[i], w.y, a1);
        }
        sts_f32(aaddr + eo0, a0);
        sts_f32(aaddr + eo1, a1);
    }
    __syncwarp();

    #pragma unroll 1
    for (int it = 0; it < MAX_ITER; it++) {
        // ---- combine: e[m] = INVC*proj[m] - INVC*mel[m] ----
        #pragma unroll
        for (int j = 0; j < 4; j++) {
            int m = lane + 32*j;
            float4 v = *reinterpret_cast<const float4*>(&S.it.acc[wid][m][0]);
            float s = (v.x + v.y) + (v.z + v.w);
            sts_f32(diffb + (unsigned)m * 4u, fmaf(s, INVC, -melI[j]));
        }
        __syncwarp();

        // ---- fused backward(it) + forward(it+1) ----
        unsigned aaddr = accb + (unsigned)mfirst * 16u;
        unsigned daddr = diffb + (unsigned)mfirst * 4u;
        float a0 = 0.f, a1 = 0.f;
        float d0 = lds_f32(daddr);
        float d1 = lds_f32(daddr + 4u);
        #pragma unroll
        for (int i = 0; i < CH; i++) {
            if (i > 0) {
                int ch = (int)((mask >> (i-1)) & 1u);
                pred_sts(aaddr, a0, ch);
                a0 = ch ? a1 : a0;
                a1 = ch ? 0.f : a1;
                aaddr += (unsigned)ch << 4;
                d0 = ch ? d1 : d0;
                pred_lds(d1, daddr + 8u, ch);     // load e[m_new+1] only on change
                daddr += (unsigned)ch << 2;
            }
            float2 w = w01[f_lo + i];
            float g  = fmaf(d1, w.y, d0 * w.x);   // grad_f = e[m]*w0 + e[m+1]*w1
            bu[i] = fmaf(MOM, bu[i], g);
            sp[i] = fmaxf(fmaf(-LR, bu[i], sp[i]), 0.f);
            a0 = fmaf(sp[i], w.x, a0);            // forward for next iteration
            a1 = fmaf(sp[i], w.y, a1);
        }
        sts_f32(aaddr + eo0, a0);
        sts_f32(aaddr + eo1, a1);
        __syncwarp();
    }

    // ---- epilogue: stage rows in shared, write (B,F,T) directly ----
    __syncthreads();            // before overlapping union reuse (cross-warp)
    {
        float* stg = &S.stage[wid][0];
        #pragma unroll
        for (int i = 0; i < CH; i++) stg[f_lo + i] = sp[i];
    }
    __syncthreads();
    {
        const int t0 = (blockIdx.x * WPB) & (TIME - 1);
        const int bb = (blockIdx.x * WPB) >> 10;
        float* ob = out + (size_t)bb * N_STFT * TIME + (size_t)t0;
        const int j  = tid & 3;      // t offset within CTA
        const int f0 = tid >> 2;
        #pragma unroll 1
        for (int f = f0; f < N_STFT; f += 32)
            ob[(size_t)f * TIME + j] = S.stage[j][f];
    }
}

// ---------------- launch ----------------
extern "C" void kernel_launch(void* const* d_in, const int* in_sizes, int n_in,
                              void* d_out, int out_size) {
    const float* mel = nullptr;   // 4*128*1024
    const float* spi = nullptr;   // 4*1024*1025
    const float* fb  = nullptr;   // 1025*128
    for (int i = 0; i < n_in; i++) {
        if      (in_sizes[i] == BATCH * N_MELS * TIME) mel = (const float*)d_in[i];
        else if (in_sizes[i] == ROWS * N_STFT)         spi = (const float*)d_in[i];
        else if (in_sizes[i] == N_STFT * N_MELS)       fb  = (const float*)d_in[i];
    }
    float* out = (float*)d_out;

    build_tables_k<<<FPAD/8, 256>>>(fb);            // 1056 warps, warp per frequency
    imel_k<<<ROWS/WPB, WPB*32>>>(mel, spi, out);
}